// round 16
// baseline (speedup 1.0000x reference)
#include <cuda_runtime.h>
#include <cuda_fp16.h>
#include <stdint.h>

#define NT 4
#define P0 100
#define P1C 100
#define P2C 100
#define NPRE 404                  // 400 W12 blocks + 4 c0f blocks

// W12 scratch, per (t,i1,i2) slice as TWO mma.m16n8k16 A-fragments. 41 MB.
__device__ __align__(16) __half g_W12[(size_t)NT * P1C * P2C * 512];
// c0 as fp16 B-fragments per (t,i0) slice. 204.8KB.
__device__ uint4 g_c0f[(size_t)NT * P0 * 32];
// Barrier state (zero-init; every run balanced back to zero by last block).
__device__ int g_done;
__device__ int g_fin;

// r = {hi:lo} packed fp16x2
__device__ __forceinline__ unsigned pack_h2(float lo, float hi) {
    unsigned r;
    asm("cvt.rn.f16x2.f32 %0, %1, %2;" : "=r"(r) : "f"(hi), "f"(lo));
    return r;
}

// ---------------------------------------------------------------------------
// ONE kernel. Blocks 0..399: W12 GEMM producer (t,i1). Blocks 400..403: c0
// B-fragments. Blocks >= 404: spin until g_done==NPRE, then lookup+pool.
// launch_bounds(256,4): regs<=64 and smem 8KB -> >=4 blocks/SM resident ->
// all NPRE producers live in wave 1 -> spin cannot deadlock.
// ---------------------------------------------------------------------------
__global__ __launch_bounds__(256, 4) void tt_fused_kernel(
        const int* __restrict__ indices, const int* __restrict__ offsets,
        const float* __restrict__ c0g, const float* __restrict__ c1g,
        const float* __restrict__ c2g, float* __restrict__ out,
        int B, int bags_per_table, int nlook) {
    __shared__ uint4 smB[512];    // c1 B-frags: [nt 16][lane 32], 8KB
    int b = blockIdx.x;
    int tid = threadIdx.x;

    if (b < NT * P1C) {
        // ================= W12 producer =================
        int t = b / P1C, i1 = b - t * P1C;

        // B-frags from this (t,i1)'s c1 slice.
        const float* c1 = c1g + (size_t)(t * P1C + i1) * 4096;
        for (int tau = tid; tau < 512; tau += 256) {
            int nt = tau >> 5, lane = tau & 31;
            int g = lane >> 2, tj = lane & 3;
            int q1 = nt >> 2, r1 = 8 * (nt & 3) + g;
            const float* row = c1 + (r1 * 4 + q1) * 32;
            uint4 v;
            v.x = pack_h2(row[2 * tj],      row[2 * tj + 1]);
            v.y = pack_h2(row[2 * tj + 8],  row[2 * tj + 9]);
            v.z = pack_h2(row[2 * tj + 16], row[2 * tj + 17]);
            v.w = pack_h2(row[2 * tj + 24], row[2 * tj + 25]);
            smB[tau] = v;
        }
        __syncthreads();

        int w = tid >> 5, lane = tid & 31;
        int g  = lane >> 2, tj = lane & 3;      // g 0..7
        int g3 = g & 3, ghi = lane >> 4;
        const float* c2tab = c2g + (size_t)t * P2C * 128;
        char* Wb = (char*)g_W12 + (size_t)(t * P1C + i1) * P2C * 1024;

        // Per-warp mt tiles; A-frags built in registers from L1-hot c2 table,
        // amortized over the 4 qd tasks of each mt.
        for (int mt = w; mt < 25; mt += 8) {
            int i2a = 4 * mt + (g >> 2), q2 = g & 3;
            const float* pa = c2tab + i2a * 128 + q2;   // + r2*4 steps r2
            const float* pb = pa + 256;                  // i2a + 2
            uint4 A0, A1;
            {   int kb = 2 * tj;                         // ks = 0
                A0.x = pack_h2(pa[kb * 4],       pa[(kb + 1) * 4]);
                A0.y = pack_h2(pb[kb * 4],       pb[(kb + 1) * 4]);
                A0.z = pack_h2(pa[(kb + 8) * 4], pa[(kb + 9) * 4]);
                A0.w = pack_h2(pb[(kb + 8) * 4], pb[(kb + 9) * 4]);
            }
            {   int kb = 16 + 2 * tj;                    // ks = 1
                A1.x = pack_h2(pa[kb * 4],       pa[(kb + 1) * 4]);
                A1.y = pack_h2(pb[kb * 4],       pb[(kb + 1) * 4]);
                A1.z = pack_h2(pa[(kb + 8) * 4], pa[(kb + 9) * 4]);
                A1.w = pack_h2(pb[(kb + 8) * 4], pb[(kb + 9) * 4]);
            }
            #pragma unroll
            for (int qd = 0; qd < 4; qd++) {
                int nt0 = 2 * qd, f = qd & 1, q1b = qd >> 1;
                unsigned pr[4], qr[4];
                const int nts[4] = {nt0, nt0 + 8, nt0 + 1, nt0 + 9};
                #pragma unroll
                for (int s = 0; s < 4; s++) {
                    uint4 Bv = smB[nts[s] * 32 + lane];
                    float d0 = 0.f, d1 = 0.f, d2 = 0.f, d3 = 0.f;
                    asm volatile(
                        "mma.sync.aligned.m16n8k16.row.col.f32.f16.f16.f32 "
                        "{%0,%1,%2,%3}, {%4,%5,%6,%7}, {%8,%9}, {%0,%1,%2,%3};"
                        : "+f"(d0), "+f"(d1), "+f"(d2), "+f"(d3)
                        : "r"(A0.x), "r"(A0.y), "r"(A0.z), "r"(A0.w),
                          "r"(Bv.x), "r"(Bv.y));
                    asm volatile(
                        "mma.sync.aligned.m16n8k16.row.col.f32.f16.f16.f32 "
                        "{%0,%1,%2,%3}, {%4,%5,%6,%7}, {%8,%9}, {%0,%1,%2,%3};"
                        : "+f"(d0), "+f"(d1), "+f"(d2), "+f"(d3)
                        : "r"(A1.x), "r"(A1.y), "r"(A1.z), "r"(A1.w),
                          "r"(Bv.z), "r"(Bv.w));
                    pr[s] = pack_h2(d0, d1);
                    qr[s] = pack_h2(d2, d3);
                }
                size_t off = (size_t)(4 * mt + ghi) * 1024 + f * 512
                           + ((q1b * 4 + g3) * 4 + tj) * 16;
                *(uint4*)(Wb + off)        = make_uint4(pr[0], pr[1], pr[2], pr[3]);
                *(uint4*)(Wb + off + 2048) = make_uint4(qr[0], qr[1], qr[2], qr[3]);
            }
        }
        __threadfence();
        __syncthreads();
        if (tid == 0) atomicAdd(&g_done, 1);
        return;
    }

    if (b < NPRE) {
        // ================= c0 B-fragment producer =================
        int tt = b - NT * P1C;
        for (int task = tid; task < P0 * 32; task += 256) {
            int sl = task >> 5, lane = task & 31;
            int g = lane >> 2, j = lane & 3;
            uint4 v = make_uint4(0u, 0u, 0u, 0u);
            if (g < 4) {
                const float* row = c0g + ((size_t)(tt * P0 + sl)) * 128 + g * 32 + 2 * j;
                float2 p0 = *(const float2*)(row);
                float2 p1 = *(const float2*)(row + 8);
                float2 p2 = *(const float2*)(row + 16);
                float2 p3 = *(const float2*)(row + 24);
                v.x = pack_h2(p0.x, p0.y);
                v.y = pack_h2(p1.x, p1.y);
                v.z = pack_h2(p2.x, p2.y);
                v.w = pack_h2(p3.x, p3.y);
            }
            g_c0f[(size_t)(tt * P0 + sl) * 32 + lane] = v;
        }
        __threadfence();
        __syncthreads();
        if (tid == 0) atomicAdd(&g_done, 1);
        return;
    }

    // ================= lookup blocks =================
    if (tid == 0) {
        while (atomicAdd(&g_done, 0) < NPRE) __nanosleep(100);
        __threadfence();
    }
    __syncthreads();

    {
        int bag = (b - NPRE) * 8 + (tid >> 5);
        int lane = tid & 31;
        if (bag < B) {
            int g = lane >> 2, j = lane & 3;
            int t = bag / bags_per_table;
            int s = offsets[bag], e = offsets[bag + 1];

            const uint4* Wt = (const uint4*)(g_W12 + (size_t)t * P1C * P2C * 512);
            const uint4* Cf = g_c0f + (size_t)t * P0 * 32;

            float d0 = 0.f, d1 = 0.f, d2 = 0.f, d3 = 0.f;

            for (int base = s; base < e; base += 32) {
                int n = min(32, e - base);
                int idx = (base + lane < e) ? indices[base + lane] : 0;
                int i0  = idx / 10000;
                int rem = idx - i0 * 10000;
                int v   = rem | (i0 << 20);

                for (int p = 0; p < n; p++) {
                    int vp = __shfl_sync(0xffffffffu, v, p);
                    const uint4* wb = Wt + (vp & 0xFFFFF) * 64;
                    const uint4* cb = Cf + (vp >> 20) * 32;
                    uint4 A0 = wb[lane];
                    uint4 A1 = wb[32 + lane];
                    uint4 Bf = cb[lane];
                    asm volatile(
                        "mma.sync.aligned.m16n8k16.row.col.f32.f16.f16.f32 "
                        "{%0,%1,%2,%3}, {%4,%5,%6,%7}, {%8,%9}, {%0,%1,%2,%3};"
                        : "+f"(d0), "+f"(d1), "+f"(d2), "+f"(d3)
                        : "r"(A0.x), "r"(A0.y), "r"(A0.z), "r"(A0.w),
                          "r"(Bf.x), "r"(Bf.y));
                    asm volatile(
                        "mma.sync.aligned.m16n8k16.row.col.f32.f16.f16.f32 "
                        "{%0,%1,%2,%3}, {%4,%5,%6,%7}, {%8,%9}, {%0,%1,%2,%3};"
                        : "+f"(d0), "+f"(d1), "+f"(d2), "+f"(d3)
                        : "r"(A1.x), "r"(A1.y), "r"(A1.z), "r"(A1.w),
                          "r"(Bf.z), "r"(Bf.w));
                }
            }

            if (j < 2) {
                float* ob = out + (size_t)bag * 64;
                ob[(2 * j) * 16 + g]         = d0;
                ob[(2 * j + 1) * 16 + g]     = d1;
                ob[(2 * j) * 16 + g + 8]     = d2;
                ob[(2 * j + 1) * 16 + g + 8] = d3;
            }
        }
    }

    // Balanced reset: last lookup block to finish zeroes both counters so the
    // next graph replay starts from a clean state.
    __syncthreads();
    if (tid == 0) {
        int f = atomicAdd(&g_fin, 1);
        if (f == nlook - 1) {
            atomicSub(&g_fin, nlook);
            atomicSub(&g_done, NPRE);
        }
    }
}

// ---------------------------------------------------------------------------
extern "C" void kernel_launch(void* const* d_in, const int* in_sizes, int n_in,
                              void* d_out, int out_size) {
    const int* indices = (const int*)d_in[0];
    const int* offsets = (const int*)d_in[1];
    const float* c0 = (const float*)d_in[2];
    const float* c1 = (const float*)d_in[3];
    const float* c2 = (const float*)d_in[4];

    int B = in_sizes[1] - 1;
    int bags_per_table = B / NT;
    int nlook = (B + 7) / 8;

    tt_fused_kernel<<<NPRE + nlook, 256>>>(
        indices, offsets, c0, c1, c2, (float*)d_out,
        B, bags_per_table, nlook);
}

// round 17
// speedup vs baseline: 1.6396x; 1.6396x over previous
#include <cuda_runtime.h>
#include <cuda_fp16.h>
#include <stdint.h>

#define NT 4
#define P0 100
#define P1C 100
#define P2C 100

// W12 scratch, per (t,i1,i2) slice as TWO mma.m16n8k16 A-fragments
// (k = r1 0..15 / 16..31). Slice = 1KB. 41 MB -> L2-resident.
__device__ __align__(16) __half g_W12[(size_t)NT * P1C * P2C * 512];

// c0 as fp16 B-fragments: per (t,i0) slice, lane l holds uint4
// {b0_f0, b1_f0, b0_f1, b1_f1}. B[k=r1][n=q0], cols 4..7 zero. 204.8KB.
__device__ uint4 g_c0f[(size_t)NT * P0 * 32];

// r = {hi:lo} packed fp16x2
__device__ __forceinline__ unsigned pack_h2(float lo, float hi) {
    unsigned r;
    asm("cvt.rn.f16x2.f32 %0, %1, %2;" : "=r"(r) : "f"(hi), "f"(lo));
    return r;
}

// ---------------------------------------------------------------------------
// Fused precompute. Blocks 0..199 = (t, i1-pair): tensor-core GEMM
//   D[(i2,q2)][(q1,r1)] = sum_r2 c2[(i2,q2)][r2] * c1[r2][(q1,r1)]
// The expensive scattered A-fragment build (c2, identical for every i1 of a
// table) is done ONCE per block and reused for both i1 values.
// Blocks 200..203: c0 -> B-fragments (one table each).
// ---------------------------------------------------------------------------
__global__ __launch_bounds__(256) void tt_precompute_kernel(
        const float* __restrict__ c1g, const float* __restrict__ c2g,
        const float* __restrict__ c0g) {
    int b = blockIdx.x;
    int tid = threadIdx.x;

    if (b >= NT * P1C / 2) {                    // ---- c0 fragment blocks ----
        int tt = b - NT * P1C / 2;
        for (int task = tid; task < P0 * 32; task += 256) {
            int sl = task >> 5, lane = task & 31;
            int g = lane >> 2, j = lane & 3;
            uint4 v = make_uint4(0u, 0u, 0u, 0u);
            if (g < 4) {
                const float* row = c0g + ((size_t)(tt * P0 + sl)) * 128 + g * 32 + 2 * j;
                float2 p0 = *(const float2*)(row);
                float2 p1 = *(const float2*)(row + 8);
                float2 p2 = *(const float2*)(row + 16);
                float2 p3 = *(const float2*)(row + 24);
                v.x = pack_h2(p0.x, p0.y);
                v.y = pack_h2(p1.x, p1.y);
                v.z = pack_h2(p2.x, p2.y);
                v.w = pack_h2(p3.x, p3.y);
            }
            g_c0f[(size_t)(tt * P0 + sl) * 32 + lane] = v;
        }
        return;
    }

    __shared__ uint4 smA[1600];   // A-frags (c2): [mt 25][ks 2][lane 32]
    __shared__ uint4 smB[512];    // B-frags (c1): [nt 16][lane 32]

    int t = b / (P1C / 2);
    int ipair = b - t * (P1C / 2);              // 0..49 -> i1 = 2*ipair + ii

    // ---- Build A fragments from c2 table ONCE (shared by both i1) ----
    const float* c2tab = c2g + (size_t)t * P2C * 128;
    for (int tau = tid; tau < 1600; tau += 256) {
        int mt = tau >> 6, ks = (tau >> 5) & 1, lane = tau & 31;
        int g = lane >> 2, tj = lane & 3;
        int i2a = 4 * mt + (g >> 2), q2 = g & 3;
        int kb = 16 * ks + 2 * tj;
        const float* pa = c2tab + i2a * 128 + q2;   // + r2*4 steps over r2
        const float* pb = pa + 2 * 128;             // i2b = i2a + 2 (rows +8)
        uint4 v;
        v.x = pack_h2(pa[kb * 4],       pa[(kb + 1) * 4]);
        v.y = pack_h2(pb[kb * 4],       pb[(kb + 1) * 4]);
        v.z = pack_h2(pa[(kb + 8) * 4], pa[(kb + 9) * 4]);
        v.w = pack_h2(pb[(kb + 8) * 4], pb[(kb + 9) * 4]);
        smA[tau] = v;
    }

    int w = tid >> 5, lane = tid & 31;
    int g3 = (lane >> 2) & 3, tj = lane & 3, ghi = lane >> 4;

    #pragma unroll
    for (int ii = 0; ii < 2; ii++) {
        int i1 = 2 * ipair + ii;

        // Protect smB against the previous iteration's readers (and make the
        // smA build visible before the first MMA).
        __syncthreads();

        // ---- Build B fragments from this (t,i1)'s c1 slice ----
        const float* c1 = c1g + (size_t)(t * P1C + i1) * 4096;
        for (int tau = tid; tau < 512; tau += 256) {
            int nt = tau >> 5, ln = tau & 31;
            int g = ln >> 2, tj2 = ln & 3;
            int q1 = nt >> 2, r1 = 8 * (nt & 3) + g;
            const float* row = c1 + (r1 * 4 + q1) * 32;
            uint4 v;
            v.x = pack_h2(row[2 * tj2],      row[2 * tj2 + 1]);
            v.y = pack_h2(row[2 * tj2 + 8],  row[2 * tj2 + 9]);
            v.z = pack_h2(row[2 * tj2 + 16], row[2 * tj2 + 17]);
            v.w = pack_h2(row[2 * tj2 + 24], row[2 * tj2 + 25]);
            smB[tau] = v;
        }
        __syncthreads();

        // ---- MMA: tasks (mt 0..24, quad 0..3) ----
        char* Wb = (char*)g_W12 + (size_t)(t * P1C + i1) * P2C * 1024;
        for (int tau = w; tau < 100; tau += 8) {
            int mt = tau >> 2, qd = tau & 3;
            int nt0 = 2 * qd, f = qd & 1, q1b = qd >> 1;
            uint4 A0 = smA[mt * 64 + lane];
            uint4 A1 = smA[mt * 64 + 32 + lane];
            unsigned pa[4], pb[4];
            const int nts[4] = {nt0, nt0 + 8, nt0 + 1, nt0 + 9};
            #pragma unroll
            for (int s = 0; s < 4; s++) {
                uint4 Bv = smB[nts[s] * 32 + lane];
                float d0 = 0.f, d1 = 0.f, d2 = 0.f, d3 = 0.f;
                asm volatile(
                    "mma.sync.aligned.m16n8k16.row.col.f32.f16.f16.f32 "
                    "{%0,%1,%2,%3}, {%4,%5,%6,%7}, {%8,%9}, {%0,%1,%2,%3};"
                    : "+f"(d0), "+f"(d1), "+f"(d2), "+f"(d3)
                    : "r"(A0.x), "r"(A0.y), "r"(A0.z), "r"(A0.w),
                      "r"(Bv.x), "r"(Bv.y));
                asm volatile(
                    "mma.sync.aligned.m16n8k16.row.col.f32.f16.f16.f32 "
                    "{%0,%1,%2,%3}, {%4,%5,%6,%7}, {%8,%9}, {%0,%1,%2,%3};"
                    : "+f"(d0), "+f"(d1), "+f"(d2), "+f"(d3)
                    : "r"(A1.x), "r"(A1.y), "r"(A1.z), "r"(A1.w),
                      "r"(Bv.z), "r"(Bv.w));
                pa[s] = pack_h2(d0, d1);
                pb[s] = pack_h2(d2, d3);
            }
            size_t off = (size_t)(4 * mt + ghi) * 1024 + f * 512
                       + ((q1b * 4 + g3) * 4 + tj) * 16;
            *(uint4*)(Wb + off)        = make_uint4(pa[0], pa[1], pa[2], pa[3]);
            *(uint4*)(Wb + off + 2048) = make_uint4(pb[0], pb[1], pb[2], pb[3]);
        }
    }
}

// ---------------------------------------------------------------------------
// Lookup + pool via HMMA. One warp per bag. Byte-identical to the proven
// 40.8us R10 version (pinned at the chip L2 cap: 1KB W12 gather per lookup).
// ---------------------------------------------------------------------------
__global__ void tt_lookup_kernel(const int* __restrict__ indices,
                                 const int* __restrict__ offsets,
                                 float* __restrict__ out,
                                 int B, int bags_per_table) {
    int bag = (int)((blockIdx.x * (size_t)blockDim.x + threadIdx.x) >> 5);
    if (bag >= B) return;
    int lane = threadIdx.x & 31;
    int g = lane >> 2, j = lane & 3;

    int t = bag / bags_per_table;
    int s = offsets[bag], e = offsets[bag + 1];

    const uint4* Wt = (const uint4*)(g_W12 + (size_t)t * P1C * P2C * 512);
    const uint4* Cf = g_c0f + (size_t)t * P0 * 32;

    float d0 = 0.f, d1 = 0.f, d2 = 0.f, d3 = 0.f;

    for (int base = s; base < e; base += 32) {
        int n = min(32, e - base);
        int idx = (base + lane < e) ? indices[base + lane] : 0;  // coalesced
        int i0  = idx / 10000;
        int rem = idx - i0 * 10000;
        int v   = rem | (i0 << 20);

        for (int p = 0; p < n; p++) {
            int vp = __shfl_sync(0xffffffffu, v, p);
            const uint4* wb = Wt + (vp & 0xFFFFF) * 64;
            const uint4* cb = Cf + (vp >> 20) * 32;
            uint4 A0 = wb[lane];
            uint4 A1 = wb[32 + lane];
            uint4 Bf = cb[lane];
            asm volatile(
                "mma.sync.aligned.m16n8k16.row.col.f32.f16.f16.f32 "
                "{%0,%1,%2,%3}, {%4,%5,%6,%7}, {%8,%9}, {%0,%1,%2,%3};"
                : "+f"(d0), "+f"(d1), "+f"(d2), "+f"(d3)
                : "r"(A0.x), "r"(A0.y), "r"(A0.z), "r"(A0.w),
                  "r"(Bf.x), "r"(Bf.y));
            asm volatile(
                "mma.sync.aligned.m16n8k16.row.col.f32.f16.f16.f32 "
                "{%0,%1,%2,%3}, {%4,%5,%6,%7}, {%8,%9}, {%0,%1,%2,%3};"
                : "+f"(d0), "+f"(d1), "+f"(d2), "+f"(d3)
                : "r"(A1.x), "r"(A1.y), "r"(A1.z), "r"(A1.w),
                  "r"(Bf.z), "r"(Bf.w));
        }
    }

    if (j < 2) {
        float* ob = out + (size_t)bag * 64;
        ob[(2 * j) * 16 + g]         = d0;
        ob[(2 * j + 1) * 16 + g]     = d1;
        ob[(2 * j) * 16 + g + 8]     = d2;
        ob[(2 * j + 1) * 16 + g + 8] = d3;
    }
}

// ---------------------------------------------------------------------------
extern "C" void kernel_launch(void* const* d_in, const int* in_sizes, int n_in,
                              void* d_out, int out_size) {
    const int* indices = (const int*)d_in[0];
    const int* offsets = (const int*)d_in[1];
    const float* c0 = (const float*)d_in[2];
    const float* c1 = (const float*)d_in[3];
    const float* c2 = (const float*)d_in[4];

    int B = in_sizes[1] - 1;
    int bags_per_table = B / NT;

    tt_precompute_kernel<<<NT * P1C / 2 + NT, 256>>>(c1, c2, c0);

    const int warps_per_block = 8;
    int blocks = (B + warps_per_block - 1) / warps_per_block;
    tt_lookup_kernel<<<blocks, warps_per_block * 32>>>(
        indices, offsets, (float*)d_out, B, bags_per_table);
}